// round 4
// baseline (speedup 1.0000x reference)
#include <cuda_runtime.h>

// Problem constants (fixed shapes)
#define B_   2
#define S_   2048
#define D_   1024
#define H_   16
#define HD_  64
#define M_TOT (B_ * S_)   // 4096

// ---------------------------------------------------------------------------
// Scratch buffers
// ---------------------------------------------------------------------------
__device__ float g_q[B_ * H_ * S_ * HD_];    // [B,H,S,HD]
__device__ float g_k[B_ * H_ * S_ * HD_];
__device__ float g_v[B_ * H_ * S_ * HD_];
__device__ float g_att[B_ * S_ * D_];        // [B,S,D]

// ---------------------------------------------------------------------------
// Helpers
// ---------------------------------------------------------------------------
__device__ __forceinline__ unsigned f2tf(float x) {
    unsigned u;
    asm("cvt.rna.tf32.f32 %0, %1;" : "=r"(u) : "f"(x));
    return u;
}

__device__ __forceinline__ void mma_tf32(float* d, const unsigned* a,
                                         unsigned b0, unsigned b1) {
    asm volatile(
        "mma.sync.aligned.m16n8k8.row.col.f32.tf32.tf32.f32 "
        "{%0,%1,%2,%3}, {%4,%5,%6,%7}, {%8,%9}, {%0,%1,%2,%3};"
        : "+f"(d[0]), "+f"(d[1]), "+f"(d[2]), "+f"(d[3])
        : "r"(a[0]), "r"(a[1]), "r"(a[2]), "r"(a[3]), "r"(b0), "r"(b1));
}

// ---------------------------------------------------------------------------
// Pipelined TF32 GEMM with permuted smem layouts (vectorized frag loads).
// CTA tile 128x128x32, 8 warps (2x4), warp tile 64x32.
//   A layout: off(r,c) = r*40 + (((c&3)+r)&3)*10 + (c>>2)
//   B layout: off(r,c) = r*132 + (c&7)*16 + (c>>3)
// ---------------------------------------------------------------------------
#define GBM 128
#define GBN 128
#define GBK 32
#define AST2 40
#define BST2 132

__global__ void __launch_bounds__(256, 2) gemm_tf32_kernel(
    const float* __restrict__ A, const float* __restrict__ W,
    const float* __restrict__ bias, float* __restrict__ out,
    int M, int N, int K, int qkv_mode)
{
    __shared__ float As[GBM * AST2];   // 20 KB
    __shared__ float Bs[GBK * BST2];   // 16.9 KB

    const int tid  = threadIdx.x;
    const int warp = tid >> 5;
    const int lane = tid & 31;
    const int g    = lane >> 2;
    const int tig  = lane & 3;
    const int wm   = (warp >> 2) * 64;      // 0, 64
    const int wn   = (warp & 3) * 32;       // 0, 32, 64, 96
    const int wn4  = wn >> 3;               // 0, 4, 8, 12
    const int bm   = blockIdx.y * GBM;
    const int bn   = blockIdx.x * GBN;

    const int arow = tid >> 1;              // 0..127
    const int acol = (tid & 1) * 16;        // 0, 16
    const int brow = tid >> 3;              // 0..31
    const int bcol = (tid & 7) * 16;        // 0..112

    float acc[16][4];
#pragma unroll
    for (int f = 0; f < 16; f++)
#pragma unroll
        for (int e = 0; e < 4; e++) acc[f][e] = 0.0f;

    const float* Aro = A + (size_t)(bm + arow) * K + acol;
    const float* Bro = W + (size_t)brow * N + bn + bcol;

    float4 ra[4], rb[4];

#pragma unroll
    for (int p = 0; p < 4; p++) ra[p] = *(const float4*)(Aro + p * 4);
#pragma unroll
    for (int p = 0; p < 4; p++) rb[p] = *(const float4*)(Bro + p * 4);

    // store tile 0
#pragma unroll
    for (int p = 0; p < 4; p++) {
        float av[4] = { ra[p].x, ra[p].y, ra[p].z, ra[p].w };
        float bv[4] = { rb[p].x, rb[p].y, rb[p].z, rb[p].w };
#pragma unroll
        for (int e = 0; e < 4; e++) {
            As[arow * AST2 + (((e) + arow) & 3) * 10 + (acol >> 2) + p] =
                __uint_as_float(f2tf(av[e]));
            int c = bcol + p * 4 + e;
            Bs[brow * BST2 + (c & 7) * 16 + (c >> 3)] =
                __uint_as_float(f2tf(bv[e]));
        }
    }
    __syncthreads();

    const int acls = ((tig + g) & 3) * 10;   // A frag class offset (rows ≡ g mod 4)

    const int NT = K / GBK;
    for (int t = 0; t < NT; t++) {
        if (t + 1 < NT) {
            const float* An = Aro + (t + 1) * GBK;
            const float* Bn = Bro + (size_t)(t + 1) * GBK * N;
#pragma unroll
            for (int p = 0; p < 4; p++) ra[p] = *(const float4*)(An + p * 4);
#pragma unroll
            for (int p = 0; p < 4; p++) rb[p] = *(const float4*)(Bn + p * 4);
        }

#pragma unroll
        for (int kk = 0; kk < GBK; kk += 8) {
            unsigned af[4][4];
#pragma unroll
            for (int i = 0; i < 4; i++) {
                int rlo = wm + i * 16 + g;
                float2 lo = *(const float2*)(As + rlo * AST2 + acls + (kk >> 2));
                float2 hi = *(const float2*)(As + (rlo + 8) * AST2 + acls + (kk >> 2));
                af[i][0] = __float_as_uint(lo.x);
                af[i][1] = __float_as_uint(hi.x);
                af[i][2] = __float_as_uint(lo.y);
                af[i][3] = __float_as_uint(hi.y);
            }
            float4 b0 = *(const float4*)(Bs + (kk + tig) * BST2 + g * 16 + wn4);
            float4 b1 = *(const float4*)(Bs + (kk + tig + 4) * BST2 + g * 16 + wn4);
            const float* pb0 = &b0.x;
            const float* pb1 = &b1.x;
#pragma unroll
            for (int i = 0; i < 4; i++)
#pragma unroll
                for (int j = 0; j < 4; j++)
                    mma_tf32(acc[i * 4 + j], af[i],
                             __float_as_uint(pb0[j]), __float_as_uint(pb1[j]));
        }
        __syncthreads();

        if (t + 1 < NT) {
#pragma unroll
            for (int p = 0; p < 4; p++) {
                float av[4] = { ra[p].x, ra[p].y, ra[p].z, ra[p].w };
                float bv[4] = { rb[p].x, rb[p].y, rb[p].z, rb[p].w };
#pragma unroll
                for (int e = 0; e < 4; e++) {
                    As[arow * AST2 + (((e) + arow) & 3) * 10 + (acol >> 2) + p] =
                        __uint_as_float(f2tf(av[e]));
                    int c = bcol + p * 4 + e;
                    Bs[brow * BST2 + (c & 7) * 16 + (c >> 3)] =
                        __uint_as_float(f2tf(bv[e]));
                }
            }
            __syncthreads();
        }
    }

    // Register epilogue
#pragma unroll
    for (int i = 0; i < 4; i++) {
#pragma unroll
        for (int j = 0; j < 4; j++) {
            const float* d = acc[i * 4 + j];
            int col = bn + wn + j * 8 + 2 * tig;
            float2 b2 = *(const float2*)(bias + col);
            int row_lo = bm + wm + i * 16 + g;
            float2 vlo = { d[0] + b2.x, d[1] + b2.y };
            float2 vhi = { d[2] + b2.x, d[3] + b2.y };
            if (qkv_mode) {
                int h = col / HD_, dd = col % HD_;
                int b0i = row_lo / S_, s0 = row_lo % S_;
                *(float2*)(out + ((size_t)((b0i * H_ + h) * S_ + s0)) * HD_ + dd) = vlo;
                int row_hi = row_lo + 8;
                int b1i = row_hi / S_, s1 = row_hi % S_;
                *(float2*)(out + ((size_t)((b1i * H_ + h) * S_ + s1)) * HD_ + dd) = vhi;
            } else {
                *(float2*)(out + (size_t)row_lo * N + col) = vlo;
                *(float2*)(out + (size_t)(row_lo + 8) * N + col) = vhi;
            }
        }
    }
}

// ---------------------------------------------------------------------------
// Flash attention v3: register S/P/O + permuted K/V smem for vector LDS.
//   K layout: off(r,c) = r*80  + (c&3)*20 + (c>>2)   (thread reads 4xfloat4/row)
//   V layout: off(r,c) = r*104 + (c&7)*12 + (c>>3)   (thread reads 4xfloat4/kc)
// ---------------------------------------------------------------------------
#define AQ  64
#define AKV 64
#define KST 80
#define VST 104

__global__ void __launch_bounds__(128) attn_kernel(
    const float* __restrict__ Qb, const float* __restrict__ Kb,
    const float* __restrict__ Vb, float* __restrict__ Ob)
{
    __shared__ float Ks[AKV * KST];   // 20 KB
    __shared__ float Vs[AKV * VST];   // 26 KB

    const int bh   = blockIdx.y;
    const int qt   = blockIdx.x;
    const int tid  = threadIdx.x;
    const int warp = tid >> 5;
    const int lane = tid & 31;
    const int g    = lane >> 2;
    const int tig  = lane & 3;

    const int qrow0 = qt * AQ + warp * 16;
    const float* Qp = Qb + ((size_t)bh * S_ + qrow0) * HD_;
    unsigned qa[8][4];
#pragma unroll
    for (int kc = 0; kc < 8; kc++) {
        int c0 = kc * 8 + tig;
        qa[kc][0] = f2tf(Qp[(size_t)g * HD_ + c0] * 0.125f);
        qa[kc][1] = f2tf(Qp[(size_t)(g + 8) * HD_ + c0] * 0.125f);
        qa[kc][2] = f2tf(Qp[(size_t)g * HD_ + c0 + 4] * 0.125f);
        qa[kc][3] = f2tf(Qp[(size_t)(g + 8) * HD_ + c0 + 4] * 0.125f);
    }

    float o[8][4];
#pragma unroll
    for (int j = 0; j < 8; j++)
#pragma unroll
        for (int e = 0; e < 4; e++) o[j][e] = 0.0f;
    float m_lo = -1e30f, m_hi = -1e30f;
    float l_lo = 0.0f,   l_hi = 0.0f;

    const unsigned FULL = 0xffffffffu;
    const int src0 = (lane & ~3) | (tig >> 1);
    const int src1 = src0 + 2;

    for (int kt = 0; kt < S_ / AKV; kt++) {
        const float* Kp = Kb + ((size_t)bh * S_ + kt * AKV) * HD_;
        const float* Vp = Vb + ((size_t)bh * S_ + kt * AKV) * HD_;
#pragma unroll
        for (int i = 0; i < 8; i++) {
            int idx = i * 128 + tid;
            int r = idx >> 4;
            int c = (idx & 15) * 4;
            float4 kv = *(const float4*)(Kp + (size_t)r * HD_ + c);
            float kvv[4] = { kv.x, kv.y, kv.z, kv.w };
            float4 vv = *(const float4*)(Vp + (size_t)r * HD_ + c);
            float vvv[4] = { vv.x, vv.y, vv.z, vv.w };
#pragma unroll
            for (int e = 0; e < 4; e++) {
                Ks[r * KST + e * 20 + (c >> 2)] = __uint_as_float(f2tf(kvv[e]));
                Vs[r * VST + ((c & 7) + e) * 12 + (c >> 3)] = __uint_as_float(f2tf(vvv[e]));
            }
        }
        __syncthreads();

        // ---- S = (scale*Q) @ K^T ----
        float s[8][4];
#pragma unroll
        for (int j = 0; j < 8; j++)
#pragma unroll
            for (int e = 0; e < 4; e++) s[j][e] = 0.0f;

#pragma unroll
        for (int j = 0; j < 8; j++) {
            const float* kb = Ks + (j * 8 + g) * KST + tig * 20;
            float4 k0 = *(const float4*)(kb);
            float4 k1 = *(const float4*)(kb + 4);
            float4 k2 = *(const float4*)(kb + 8);
            float4 k3 = *(const float4*)(kb + 12);
            float ka[16] = { k0.x, k0.y, k0.z, k0.w, k1.x, k1.y, k1.z, k1.w,
                             k2.x, k2.y, k2.z, k2.w, k3.x, k3.y, k3.z, k3.w };
#pragma unroll
            for (int kc = 0; kc < 8; kc++)
                mma_tf32(s[j], qa[kc],
                         __float_as_uint(ka[2 * kc]), __float_as_uint(ka[2 * kc + 1]));
        }

        // ---- Online softmax ----
        float mx_lo = -1e30f, mx_hi = -1e30f;
#pragma unroll
        for (int j = 0; j < 8; j++) {
            mx_lo = fmaxf(mx_lo, fmaxf(s[j][0], s[j][1]));
            mx_hi = fmaxf(mx_hi, fmaxf(s[j][2], s[j][3]));
        }
        mx_lo = fmaxf(mx_lo, __shfl_xor_sync(FULL, mx_lo, 1));
        mx_lo = fmaxf(mx_lo, __shfl_xor_sync(FULL, mx_lo, 2));
        mx_hi = fmaxf(mx_hi, __shfl_xor_sync(FULL, mx_hi, 1));
        mx_hi = fmaxf(mx_hi, __shfl_xor_sync(FULL, mx_hi, 2));

        float mn_lo = fmaxf(m_lo, mx_lo);
        float mn_hi = fmaxf(m_hi, mx_hi);
        float al_lo = __expf(m_lo - mn_lo);
        float al_hi = __expf(m_hi - mn_hi);
        m_lo = mn_lo; m_hi = mn_hi;

        float sum_lo = 0.0f, sum_hi = 0.0f;
#pragma unroll
        for (int j = 0; j < 8; j++) {
            float p0 = __expf(s[j][0] - mn_lo);
            float p1 = __expf(s[j][1] - mn_lo);
            float p2 = __expf(s[j][2] - mn_hi);
            float p3 = __expf(s[j][3] - mn_hi);
            sum_lo += p0 + p1;
            sum_hi += p2 + p3;
            s[j][0] = __uint_as_float(f2tf(p0));
            s[j][1] = __uint_as_float(f2tf(p1));
            s[j][2] = __uint_as_float(f2tf(p2));
            s[j][3] = __uint_as_float(f2tf(p3));
        }
        sum_lo += __shfl_xor_sync(FULL, sum_lo, 1);
        sum_lo += __shfl_xor_sync(FULL, sum_lo, 2);
        sum_hi += __shfl_xor_sync(FULL, sum_hi, 1);
        sum_hi += __shfl_xor_sync(FULL, sum_hi, 2);
        l_lo = l_lo * al_lo + sum_lo;
        l_hi = l_hi * al_hi + sum_hi;

#pragma unroll
        for (int j = 0; j < 8; j++) {
            o[j][0] *= al_lo; o[j][1] *= al_lo;
            o[j][2] *= al_hi; o[j][3] *= al_hi;
        }

        // ---- O += P @ V ----
#pragma unroll
        for (int kc = 0; kc < 8; kc++) {
            float v00 = __shfl_sync(FULL, s[kc][0], src0);
            float v01 = __shfl_sync(FULL, s[kc][1], src0);
            float v20 = __shfl_sync(FULL, s[kc][2], src0);
            float v21 = __shfl_sync(FULL, s[kc][3], src0);
            float w00 = __shfl_sync(FULL, s[kc][0], src1);
            float w01 = __shfl_sync(FULL, s[kc][1], src1);
            float w20 = __shfl_sync(FULL, s[kc][2], src1);
            float w21 = __shfl_sync(FULL, s[kc][3], src1);
            unsigned pa[4];
            pa[0] = __float_as_uint((tig & 1) ? v01 : v00);
            pa[1] = __float_as_uint((tig & 1) ? v21 : v20);
            pa[2] = __float_as_uint((tig & 1) ? w01 : w00);
            pa[3] = __float_as_uint((tig & 1) ? w21 : w20);

            const float* vb0p = Vs + (kc * 8 + tig) * VST + g * 12;
            const float* vb1p = Vs + (kc * 8 + tig + 4) * VST + g * 12;
            float4 a0 = *(const float4*)(vb0p);
            float4 a1 = *(const float4*)(vb0p + 4);
            float4 c0 = *(const float4*)(vb1p);
            float4 c1 = *(const float4*)(vb1p + 4);
            float vb0[8] = { a0.x, a0.y, a0.z, a0.w, a1.x, a1.y, a1.z, a1.w };
            float vb1[8] = { c0.x, c0.y, c0.z, c0.w, c1.x, c1.y, c1.z, c1.w };
#pragma unroll
            for (int jn = 0; jn < 8; jn++)
                mma_tf32(o[jn], pa,
                         __float_as_uint(vb0[jn]), __float_as_uint(vb1[jn]));
        }
        __syncthreads();
    }

    float inv_lo = 1.0f / l_lo;
    float inv_hi = 1.0f / l_hi;
    int b = bh / H_, h = bh % H_;
    float* orow_lo = Ob + ((size_t)(b * S_ + qrow0 + g)) * D_ + h * HD_;
    float* orow_hi = Ob + ((size_t)(b * S_ + qrow0 + g + 8)) * D_ + h * HD_;
#pragma unroll
    for (int jn = 0; jn < 8; jn++) {
        float2 wlo = { o[jn][0] * inv_lo, o[jn][1] * inv_lo };
        float2 whi = { o[jn][2] * inv_hi, o[jn][3] * inv_hi };
        *(float2*)(orow_lo + jn * 8 + 2 * tig) = wlo;
        *(float2*)(orow_hi + jn * 8 + 2 * tig) = whi;
    }
}

// ---------------------------------------------------------------------------
// Launch
// ---------------------------------------------------------------------------
extern "C" void kernel_launch(void* const* d_in, const int* in_sizes, int n_in,
                              void* d_out, int out_size)
{
    (void)in_sizes; (void)n_in; (void)out_size;
    const float* x  = (const float*)d_in[0];
    const float* Wq = (const float*)d_in[1];
    const float* bq = (const float*)d_in[2];
    const float* Wk = (const float*)d_in[3];
    const float* bk = (const float*)d_in[4];
    const float* Wv = (const float*)d_in[5];
    const float* bv = (const float*)d_in[6];
    const float* Wo = (const float*)d_in[7];
    const float* bo = (const float*)d_in[8];
    float* out = (float*)d_out;

    void *pq, *pk, *pv, *patt;
    cudaGetSymbolAddress(&pq, g_q);
    cudaGetSymbolAddress(&pk, g_k);
    cudaGetSymbolAddress(&pv, g_v);
    cudaGetSymbolAddress(&patt, g_att);
    float* qb = (float*)pq;
    float* kb = (float*)pk;
    float* vb = (float*)pv;
    float* ab = (float*)patt;

    dim3 ggrid(D_ / GBN, M_TOT / GBM);   // (8, 32)
    gemm_tf32_kernel<<<ggrid, 256>>>(x, Wq, bq, qb, M_TOT, D_, D_, 1);
    gemm_tf32_kernel<<<ggrid, 256>>>(x, Wk, bk, kb, M_TOT, D_, D_, 1);
    gemm_tf32_kernel<<<ggrid, 256>>>(x, Wv, bv, vb, M_TOT, D_, D_, 1);

    dim3 agrid(S_ / AQ, B_ * H_);        // (32, 32)
    attn_kernel<<<agrid, 128>>>(qb, kb, vb, ab);

    gemm_tf32_kernel<<<ggrid, 256>>>(ab, Wo, bo, out, M_TOT, D_, D_, 0);
}

// round 5
// speedup vs baseline: 1.1657x; 1.1657x over previous
#include <cuda_runtime.h>

// Problem constants (fixed shapes)
#define B_   2
#define S_   2048
#define D_   1024
#define H_   16
#define HD_  64
#define M_TOT (B_ * S_)   // 4096

// ---------------------------------------------------------------------------
// Scratch buffers
// ---------------------------------------------------------------------------
__device__ float g_q[B_ * H_ * S_ * HD_];    // [B,H,S,HD]
__device__ float g_k[B_ * H_ * S_ * HD_];
__device__ float g_v[B_ * H_ * S_ * HD_];
__device__ float g_att[B_ * S_ * D_];        // [B,S,D]

// ---------------------------------------------------------------------------
// Helpers
// ---------------------------------------------------------------------------
__device__ __forceinline__ unsigned f2tf(float x) {
    unsigned u;
    asm("cvt.rna.tf32.f32 %0, %1;" : "=r"(u) : "f"(x));
    return u;
}

__device__ __forceinline__ void mma_tf32(float* d, const unsigned* a,
                                         unsigned b0, unsigned b1) {
    asm volatile(
        "mma.sync.aligned.m16n8k8.row.col.f32.tf32.tf32.f32 "
        "{%0,%1,%2,%3}, {%4,%5,%6,%7}, {%8,%9}, {%0,%1,%2,%3};"
        : "+f"(d[0]), "+f"(d[1]), "+f"(d[2]), "+f"(d[3])
        : "r"(a[0]), "r"(a[1]), "r"(a[2]), "r"(a[3]), "r"(b0), "r"(b1));
}

__device__ __forceinline__ void cp_async16(void* smem_dst, const void* gmem_src) {
    unsigned saddr = (unsigned)__cvta_generic_to_shared(smem_dst);
    asm volatile("cp.async.cg.shared.global [%0], [%1], 16;"
                 :: "r"(saddr), "l"(gmem_src));
}

// ---------------------------------------------------------------------------
// Pipelined TF32 GEMM (R3 version): out = A[M,K] @ W[K,N] + bias
// CTA tile 128x128x32, 8 warps (2x4), warp tile 64x32, register prefetch.
// ---------------------------------------------------------------------------
#define GBM 128
#define GBN 128
#define GBK 32
#define GASTR 36
#define GBSTR 136

__global__ void __launch_bounds__(256, 2) gemm_tf32_kernel(
    const float* __restrict__ A, const float* __restrict__ W,
    const float* __restrict__ bias, float* __restrict__ out,
    int M, int N, int K, int qkv_mode)
{
    __shared__ float As[GBM * GASTR];
    __shared__ float Bs[GBK * GBSTR];

    const int tid  = threadIdx.x;
    const int warp = tid >> 5;
    const int lane = tid & 31;
    const int g    = lane >> 2;
    const int tig  = lane & 3;
    const int wm   = (warp >> 2) * 64;
    const int wn   = (warp & 3) * 32;
    const int bm   = blockIdx.y * GBM;
    const int bn   = blockIdx.x * GBN;

    const int arow = tid >> 1;
    const int acol = (tid & 1) * 16;
    const int brow = tid >> 3;
    const int bcol = (tid & 7) * 16;

    float acc[16][4];
#pragma unroll
    for (int f = 0; f < 16; f++)
#pragma unroll
        for (int e = 0; e < 4; e++) acc[f][e] = 0.0f;

    const float* Aro = A + (size_t)(bm + arow) * K + acol;
    const float* Bro = W + (size_t)brow * N + bn + bcol;

    float4 ra[4], rb[4];

#pragma unroll
    for (int p = 0; p < 4; p++) ra[p] = *(const float4*)(Aro + p * 4);
#pragma unroll
    for (int p = 0; p < 4; p++) rb[p] = *(const float4*)(Bro + p * 4);
#pragma unroll
    for (int p = 0; p < 4; p++) {
        uint4 t = { f2tf(ra[p].x), f2tf(ra[p].y), f2tf(ra[p].z), f2tf(ra[p].w) };
        *(uint4*)(As + arow * GASTR + acol + p * 4) = t;
        uint4 u = { f2tf(rb[p].x), f2tf(rb[p].y), f2tf(rb[p].z), f2tf(rb[p].w) };
        *(uint4*)(Bs + brow * GBSTR + bcol + p * 4) = u;
    }
    __syncthreads();

    const int NT = K / GBK;
    for (int t = 0; t < NT; t++) {
        if (t + 1 < NT) {
            const float* An = Aro + (t + 1) * GBK;
            const float* Bn = Bro + (size_t)(t + 1) * GBK * N;
#pragma unroll
            for (int p = 0; p < 4; p++) ra[p] = *(const float4*)(An + p * 4);
#pragma unroll
            for (int p = 0; p < 4; p++) rb[p] = *(const float4*)(Bn + p * 4);
        }

#pragma unroll
        for (int kk = 0; kk < GBK; kk += 8) {
            unsigned af[4][4];
#pragma unroll
            for (int i = 0; i < 4; i++) {
                const float* base = As + (wm + i * 16 + g) * GASTR + kk + tig;
                af[i][0] = __float_as_uint(base[0]);
                af[i][1] = __float_as_uint(base[8 * GASTR]);
                af[i][2] = __float_as_uint(base[4]);
                af[i][3] = __float_as_uint(base[8 * GASTR + 4]);
            }
            unsigned bf[4][2];
#pragma unroll
            for (int j = 0; j < 4; j++) {
                bf[j][0] = __float_as_uint(Bs[(kk + tig) * GBSTR + wn + j * 8 + g]);
                bf[j][1] = __float_as_uint(Bs[(kk + tig + 4) * GBSTR + wn + j * 8 + g]);
            }
#pragma unroll
            for (int i = 0; i < 4; i++)
#pragma unroll
                for (int j = 0; j < 4; j++)
                    mma_tf32(acc[i * 4 + j], af[i], bf[j][0], bf[j][1]);
        }
        __syncthreads();

        if (t + 1 < NT) {
#pragma unroll
            for (int p = 0; p < 4; p++) {
                uint4 ta = { f2tf(ra[p].x), f2tf(ra[p].y), f2tf(ra[p].z), f2tf(ra[p].w) };
                *(uint4*)(As + arow * GASTR + acol + p * 4) = ta;
                uint4 tb = { f2tf(rb[p].x), f2tf(rb[p].y), f2tf(rb[p].z), f2tf(rb[p].w) };
                *(uint4*)(Bs + brow * GBSTR + bcol + p * 4) = tb;
            }
            __syncthreads();
        }
    }

#pragma unroll
    for (int i = 0; i < 4; i++) {
#pragma unroll
        for (int j = 0; j < 4; j++) {
            const float* d = acc[i * 4 + j];
            int col = bn + wn + j * 8 + 2 * tig;
            float2 b2 = *(const float2*)(bias + col);
            int row_lo = bm + wm + i * 16 + g;
            float2 vlo = { d[0] + b2.x, d[1] + b2.y };
            float2 vhi = { d[2] + b2.x, d[3] + b2.y };
            if (qkv_mode) {
                int h = col / HD_, dd = col % HD_;
                int b0i = row_lo / S_, s0 = row_lo % S_;
                *(float2*)(out + ((size_t)((b0i * H_ + h) * S_ + s0)) * HD_ + dd) = vlo;
                int row_hi = row_lo + 8;
                int b1i = row_hi / S_, s1 = row_hi % S_;
                *(float2*)(out + ((size_t)((b1i * H_ + h) * S_ + s1)) * HD_ + dd) = vhi;
            } else {
                *(float2*)(out + (size_t)row_lo * N + col) = vlo;
                *(float2*)(out + (size_t)(row_lo + 8) * N + col) = vhi;
            }
        }
    }
}

// ---------------------------------------------------------------------------
// Flash attention v4: register S/P/O + DOUBLE-BUFFERED cp.async K/V pipeline.
// Raw fp32 in smem; tf32 cvt moved to fragment-load time (same arithmetic).
// 4 warps, Q tile 64, KV tile 64. Dynamic smem: 2 x (K+V) = 68 KB.
// ---------------------------------------------------------------------------
#define AQ  64
#define AKV 64
#define AST 68
#define ATILE (AKV * AST)              // floats per K or V buffer

extern __shared__ float attn_sm[];

__global__ void __launch_bounds__(128) attn_kernel(
    const float* __restrict__ Qb, const float* __restrict__ Kb,
    const float* __restrict__ Vb, float* __restrict__ Ob)
{
    float* Ks0 = attn_sm;
    float* Vs0 = attn_sm + ATILE;
    float* Ks1 = attn_sm + 2 * ATILE;
    float* Vs1 = attn_sm + 3 * ATILE;

    const int bh   = blockIdx.y;
    const int qt   = blockIdx.x;
    const int tid  = threadIdx.x;
    const int warp = tid >> 5;
    const int lane = tid & 31;
    const int g    = lane >> 2;
    const int tig  = lane & 3;

    // per-thread cp.async slots: 8 rows of 16B for K, 8 for V
    const int lr = tid >> 4;           // 0..7  (row block)
    const int lc = (tid & 15) * 4;     // 0..60 (col)

    const float* Kbase = Kb + (size_t)bh * S_ * HD_;
    const float* Vbase = Vb + (size_t)bh * S_ * HD_;

    // ---- Prologue: issue tile 0 loads ----
    {
        const float* Kp = Kbase;
        const float* Vp = Vbase;
#pragma unroll
        for (int i = 0; i < 8; i++) {
            int r = i * 8 + lr;
            cp_async16(Ks0 + r * AST + lc, Kp + (size_t)r * HD_ + lc);
            cp_async16(Vs0 + r * AST + lc, Vp + (size_t)r * HD_ + lc);
        }
        asm volatile("cp.async.commit_group;");
    }

    // ---- Load Q fragments once (scale folded) ----
    const int qrow0 = qt * AQ + warp * 16;
    const float* Qp = Qb + ((size_t)bh * S_ + qrow0) * HD_;
    unsigned qa[8][4];
#pragma unroll
    for (int kc = 0; kc < 8; kc++) {
        int c0 = kc * 8 + tig;
        qa[kc][0] = f2tf(Qp[(size_t)g * HD_ + c0] * 0.125f);
        qa[kc][1] = f2tf(Qp[(size_t)(g + 8) * HD_ + c0] * 0.125f);
        qa[kc][2] = f2tf(Qp[(size_t)g * HD_ + c0 + 4] * 0.125f);
        qa[kc][3] = f2tf(Qp[(size_t)(g + 8) * HD_ + c0 + 4] * 0.125f);
    }

    float o[8][4];
#pragma unroll
    for (int j = 0; j < 8; j++)
#pragma unroll
        for (int e = 0; e < 4; e++) o[j][e] = 0.0f;
    float m_lo = -1e30f, m_hi = -1e30f;
    float l_lo = 0.0f,   l_hi = 0.0f;

    const unsigned FULL = 0xffffffffu;
    const int src0 = (lane & ~3) | (tig >> 1);
    const int src1 = src0 + 2;

    const int NT = S_ / AKV;
    for (int kt = 0; kt < NT; kt++) {
        // Issue next tile's loads into the other buffer (overlaps compute)
        if (kt + 1 < NT) {
            float* Kd = (kt & 1) ? Ks0 : Ks1;
            float* Vd = (kt & 1) ? Vs0 : Vs1;
            const float* Kp = Kbase + (size_t)(kt + 1) * AKV * HD_;
            const float* Vp = Vbase + (size_t)(kt + 1) * AKV * HD_;
#pragma unroll
            for (int i = 0; i < 8; i++) {
                int r = i * 8 + lr;
                cp_async16(Kd + r * AST + lc, Kp + (size_t)r * HD_ + lc);
                cp_async16(Vd + r * AST + lc, Vp + (size_t)r * HD_ + lc);
            }
            asm volatile("cp.async.commit_group;");
            asm volatile("cp.async.wait_group 1;");
        } else {
            asm volatile("cp.async.wait_group 0;");
        }
        __syncthreads();

        const float* Ks = (kt & 1) ? Ks1 : Ks0;
        const float* Vs = (kt & 1) ? Vs1 : Vs0;

        // ---- S = (scale*Q) @ K^T  (cvt at load) ----
        float s[8][4];
#pragma unroll
        for (int j = 0; j < 8; j++)
#pragma unroll
            for (int e = 0; e < 4; e++) s[j][e] = 0.0f;

#pragma unroll
        for (int kc = 0; kc < 8; kc++) {
            int c0 = kc * 8 + tig;
#pragma unroll
            for (int j = 0; j < 8; j++) {
                unsigned b0 = f2tf(Ks[(j * 8 + g) * AST + c0]);
                unsigned b1 = f2tf(Ks[(j * 8 + g) * AST + c0 + 4]);
                mma_tf32(s[j], qa[kc], b0, b1);
            }
        }

        // ---- Online softmax ----
        float mx_lo = -1e30f, mx_hi = -1e30f;
#pragma unroll
        for (int j = 0; j < 8; j++) {
            mx_lo = fmaxf(mx_lo, fmaxf(s[j][0], s[j][1]));
            mx_hi = fmaxf(mx_hi, fmaxf(s[j][2], s[j][3]));
        }
        mx_lo = fmaxf(mx_lo, __shfl_xor_sync(FULL, mx_lo, 1));
        mx_lo = fmaxf(mx_lo, __shfl_xor_sync(FULL, mx_lo, 2));
        mx_hi = fmaxf(mx_hi, __shfl_xor_sync(FULL, mx_hi, 1));
        mx_hi = fmaxf(mx_hi, __shfl_xor_sync(FULL, mx_hi, 2));

        float mn_lo = fmaxf(m_lo, mx_lo);
        float mn_hi = fmaxf(m_hi, mx_hi);
        float al_lo = __expf(m_lo - mn_lo);
        float al_hi = __expf(m_hi - mn_hi);
        m_lo = mn_lo; m_hi = mn_hi;

        float sum_lo = 0.0f, sum_hi = 0.0f;
#pragma unroll
        for (int j = 0; j < 8; j++) {
            float p0 = __expf(s[j][0] - mn_lo);
            float p1 = __expf(s[j][1] - mn_lo);
            float p2 = __expf(s[j][2] - mn_hi);
            float p3 = __expf(s[j][3] - mn_hi);
            sum_lo += p0 + p1;
            sum_hi += p2 + p3;
            s[j][0] = __uint_as_float(f2tf(p0));
            s[j][1] = __uint_as_float(f2tf(p1));
            s[j][2] = __uint_as_float(f2tf(p2));
            s[j][3] = __uint_as_float(f2tf(p3));
        }
        sum_lo += __shfl_xor_sync(FULL, sum_lo, 1);
        sum_lo += __shfl_xor_sync(FULL, sum_lo, 2);
        sum_hi += __shfl_xor_sync(FULL, sum_hi, 1);
        sum_hi += __shfl_xor_sync(FULL, sum_hi, 2);
        l_lo = l_lo * al_lo + sum_lo;
        l_hi = l_hi * al_hi + sum_hi;

#pragma unroll
        for (int j = 0; j < 8; j++) {
            o[j][0] *= al_lo; o[j][1] *= al_lo;
            o[j][2] *= al_hi; o[j][3] *= al_hi;
        }

        // ---- O += P @ V  (cvt at load) ----
#pragma unroll
        for (int kc = 0; kc < 8; kc++) {
            float v00 = __shfl_sync(FULL, s[kc][0], src0);
            float v01 = __shfl_sync(FULL, s[kc][1], src0);
            float v20 = __shfl_sync(FULL, s[kc][2], src0);
            float v21 = __shfl_sync(FULL, s[kc][3], src0);
            float w00 = __shfl_sync(FULL, s[kc][0], src1);
            float w01 = __shfl_sync(FULL, s[kc][1], src1);
            float w20 = __shfl_sync(FULL, s[kc][2], src1);
            float w21 = __shfl_sync(FULL, s[kc][3], src1);
            unsigned pa[4];
            pa[0] = __float_as_uint((tig & 1) ? v01 : v00);
            pa[1] = __float_as_uint((tig & 1) ? v21 : v20);
            pa[2] = __float_as_uint((tig & 1) ? w01 : w00);
            pa[3] = __float_as_uint((tig & 1) ? w21 : w20);

            int r0 = (kc * 8 + tig) * AST;
            int r1 = (kc * 8 + tig + 4) * AST;
#pragma unroll
            for (int jn = 0; jn < 8; jn++) {
                unsigned b0 = f2tf(Vs[r0 + jn * 8 + g]);
                unsigned b1 = f2tf(Vs[r1 + jn * 8 + g]);
                mma_tf32(o[jn], pa, b0, b1);
            }
        }
        __syncthreads();
    }

    // ---- Normalize, write to [B,S,D] ----
    float inv_lo = 1.0f / l_lo;
    float inv_hi = 1.0f / l_hi;
    int b = bh / H_, h = bh % H_;
    float* orow_lo = Ob + ((size_t)(b * S_ + qrow0 + g)) * D_ + h * HD_;
    float* orow_hi = Ob + ((size_t)(b * S_ + qrow0 + g + 8)) * D_ + h * HD_;
#pragma unroll
    for (int jn = 0; jn < 8; jn++) {
        float2 wlo = { o[jn][0] * inv_lo, o[jn][1] * inv_lo };
        float2 whi = { o[jn][2] * inv_hi, o[jn][3] * inv_hi };
        *(float2*)(orow_lo + jn * 8 + 2 * tig) = wlo;
        *(float2*)(orow_hi + jn * 8 + 2 * tig) = whi;
    }
}

// ---------------------------------------------------------------------------
// Launch
// ---------------------------------------------------------------------------
extern "C" void kernel_launch(void* const* d_in, const int* in_sizes, int n_in,
                              void* d_out, int out_size)
{
    (void)in_sizes; (void)n_in; (void)out_size;
    const float* x  = (const float*)d_in[0];
    const float* Wq = (const float*)d_in[1];
    const float* bq = (const float*)d_in[2];
    const float* Wk = (const float*)d_in[3];
    const float* bk = (const float*)d_in[4];
    const float* Wv = (const float*)d_in[5];
    const float* bv = (const float*)d_in[6];
    const float* Wo = (const float*)d_in[7];
    const float* bo = (const float*)d_in[8];
    float* out = (float*)d_out;

    void *pq, *pk, *pv, *patt;
    cudaGetSymbolAddress(&pq, g_q);
    cudaGetSymbolAddress(&pk, g_k);
    cudaGetSymbolAddress(&pv, g_v);
    cudaGetSymbolAddress(&patt, g_att);
    float* qb = (float*)pq;
    float* kb = (float*)pk;
    float* vb = (float*)pv;
    float* ab = (float*)patt;

    const int ATT_SMEM = 4 * ATILE * (int)sizeof(float);   // 69632 B
    cudaFuncSetAttribute(attn_kernel, cudaFuncAttributeMaxDynamicSharedMemorySize, ATT_SMEM);

    dim3 ggrid(D_ / GBN, M_TOT / GBM);   // (8, 32)
    gemm_tf32_kernel<<<ggrid, 256>>>(x, Wq, bq, qb, M_TOT, D_, D_, 1);
    gemm_tf32_kernel<<<ggrid, 256>>>(x, Wk, bk, kb, M_TOT, D_, D_, 1);
    gemm_tf32_kernel<<<ggrid, 256>>>(x, Wv, bv, vb, M_TOT, D_, D_, 1);

    dim3 agrid(S_ / AQ, B_ * H_);        // (32, 32)
    attn_kernel<<<agrid, 128, ATT_SMEM>>>(qb, kb, vb, ab);

    gemm_tf32_kernel<<<ggrid, 256>>>(ab, Wo, bo, out, M_TOT, D_, D_, 0);
}

// round 6
// speedup vs baseline: 1.2146x; 1.0419x over previous
#include <cuda_runtime.h>

// Problem constants (fixed shapes)
#define B_   2
#define S_   2048
#define D_   1024
#define H_   16
#define HD_  64
#define M_TOT (B_ * S_)   // 4096

// ---------------------------------------------------------------------------
// Scratch buffers. g_q/g_k/g_v hold tf32-ROUNDED bit patterns (Q pre-scaled
// by 1/sqrt(HD)); g_att is plain fp32.
// ---------------------------------------------------------------------------
__device__ float g_q[B_ * H_ * S_ * HD_];    // [B,H,S,HD]
__device__ float g_k[B_ * H_ * S_ * HD_];
__device__ float g_v[B_ * H_ * S_ * HD_];
__device__ float g_att[B_ * S_ * D_];        // [B,S,D]

// ---------------------------------------------------------------------------
// Helpers
// ---------------------------------------------------------------------------
__device__ __forceinline__ unsigned f2tf(float x) {
    unsigned u;
    asm("cvt.rna.tf32.f32 %0, %1;" : "=r"(u) : "f"(x));
    return u;
}

__device__ __forceinline__ void mma_tf32(float* d, const unsigned* a,
                                         unsigned b0, unsigned b1) {
    asm volatile(
        "mma.sync.aligned.m16n8k8.row.col.f32.tf32.tf32.f32 "
        "{%0,%1,%2,%3}, {%4,%5,%6,%7}, {%8,%9}, {%0,%1,%2,%3};"
        : "+f"(d[0]), "+f"(d[1]), "+f"(d[2]), "+f"(d[3])
        : "r"(a[0]), "r"(a[1]), "r"(a[2]), "r"(a[3]), "r"(b0), "r"(b1));
}

__device__ __forceinline__ void cp_async16(void* smem_dst, const void* gmem_src) {
    unsigned saddr = (unsigned)__cvta_generic_to_shared(smem_dst);
    asm volatile("cp.async.cg.shared.global [%0], [%1], 16;"
                 :: "r"(saddr), "l"(gmem_src));
}

// ---------------------------------------------------------------------------
// Pipelined TF32 GEMM: out = A[M,K] @ W[K,N] + bias
// qkv_mode=1: scatter to [B,H,S,HD] writing tf32 bits scaled by oscale.
// qkv_mode=0: plain fp32 row-major [M,N].
// ---------------------------------------------------------------------------
#define GBM 128
#define GBN 128
#define GBK 32
#define GASTR 36
#define GBSTR 136

__global__ void __launch_bounds__(256, 2) gemm_tf32_kernel(
    const float* __restrict__ A, const float* __restrict__ W,
    const float* __restrict__ bias, float* __restrict__ out,
    int M, int N, int K, int qkv_mode, float oscale)
{
    __shared__ float As[GBM * GASTR];
    __shared__ float Bs[GBK * GBSTR];

    const int tid  = threadIdx.x;
    const int warp = tid >> 5;
    const int lane = tid & 31;
    const int g    = lane >> 2;
    const int tig  = lane & 3;
    const int wm   = (warp >> 2) * 64;
    const int wn   = (warp & 3) * 32;
    const int bm   = blockIdx.y * GBM;
    const int bn   = blockIdx.x * GBN;

    const int arow = tid >> 1;
    const int acol = (tid & 1) * 16;
    const int brow = tid >> 3;
    const int bcol = (tid & 7) * 16;

    float acc[16][4];
#pragma unroll
    for (int f = 0; f < 16; f++)
#pragma unroll
        for (int e = 0; e < 4; e++) acc[f][e] = 0.0f;

    const float* Aro = A + (size_t)(bm + arow) * K + acol;
    const float* Bro = W + (size_t)brow * N + bn + bcol;

    float4 ra[4], rb[4];

#pragma unroll
    for (int p = 0; p < 4; p++) ra[p] = *(const float4*)(Aro + p * 4);
#pragma unroll
    for (int p = 0; p < 4; p++) rb[p] = *(const float4*)(Bro + p * 4);
#pragma unroll
    for (int p = 0; p < 4; p++) {
        uint4 t = { f2tf(ra[p].x), f2tf(ra[p].y), f2tf(ra[p].z), f2tf(ra[p].w) };
        *(uint4*)(As + arow * GASTR + acol + p * 4) = t;
        uint4 u = { f2tf(rb[p].x), f2tf(rb[p].y), f2tf(rb[p].z), f2tf(rb[p].w) };
        *(uint4*)(Bs + brow * GBSTR + bcol + p * 4) = u;
    }
    __syncthreads();

    const int NT = K / GBK;
    for (int t = 0; t < NT; t++) {
        if (t + 1 < NT) {
            const float* An = Aro + (t + 1) * GBK;
            const float* Bn = Bro + (size_t)(t + 1) * GBK * N;
#pragma unroll
            for (int p = 0; p < 4; p++) ra[p] = *(const float4*)(An + p * 4);
#pragma unroll
            for (int p = 0; p < 4; p++) rb[p] = *(const float4*)(Bn + p * 4);
        }

#pragma unroll
        for (int kk = 0; kk < GBK; kk += 8) {
            unsigned af[4][4];
#pragma unroll
            for (int i = 0; i < 4; i++) {
                const float* base = As + (wm + i * 16 + g) * GASTR + kk + tig;
                af[i][0] = __float_as_uint(base[0]);
                af[i][1] = __float_as_uint(base[8 * GASTR]);
                af[i][2] = __float_as_uint(base[4]);
                af[i][3] = __float_as_uint(base[8 * GASTR + 4]);
            }
            unsigned bf[4][2];
#pragma unroll
            for (int j = 0; j < 4; j++) {
                bf[j][0] = __float_as_uint(Bs[(kk + tig) * GBSTR + wn + j * 8 + g]);
                bf[j][1] = __float_as_uint(Bs[(kk + tig + 4) * GBSTR + wn + j * 8 + g]);
            }
#pragma unroll
            for (int i = 0; i < 4; i++)
#pragma unroll
                for (int j = 0; j < 4; j++)
                    mma_tf32(acc[i * 4 + j], af[i], bf[j][0], bf[j][1]);
        }
        __syncthreads();

        if (t + 1 < NT) {
#pragma unroll
            for (int p = 0; p < 4; p++) {
                uint4 ta = { f2tf(ra[p].x), f2tf(ra[p].y), f2tf(ra[p].z), f2tf(ra[p].w) };
                *(uint4*)(As + arow * GASTR + acol + p * 4) = ta;
                uint4 tb = { f2tf(rb[p].x), f2tf(rb[p].y), f2tf(rb[p].z), f2tf(rb[p].w) };
                *(uint4*)(Bs + brow * GBSTR + bcol + p * 4) = tb;
            }
            __syncthreads();
        }
    }

#pragma unroll
    for (int i = 0; i < 4; i++) {
#pragma unroll
        for (int j = 0; j < 4; j++) {
            const float* d = acc[i * 4 + j];
            int col = bn + wn + j * 8 + 2 * tig;
            float2 b2 = *(const float2*)(bias + col);
            int row_lo = bm + wm + i * 16 + g;
            float2 vlo = { d[0] + b2.x, d[1] + b2.y };
            float2 vhi = { d[2] + b2.x, d[3] + b2.y };
            if (qkv_mode) {
                // write tf32-rounded bits (scaled) for the attention kernel
                uint2 tlo = { f2tf(vlo.x * oscale), f2tf(vlo.y * oscale) };
                uint2 thi = { f2tf(vhi.x * oscale), f2tf(vhi.y * oscale) };
                int h = col / HD_, dd = col % HD_;
                int b0i = row_lo / S_, s0 = row_lo % S_;
                *(uint2*)(out + ((size_t)((b0i * H_ + h) * S_ + s0)) * HD_ + dd) = tlo;
                int row_hi = row_lo + 8;
                int b1i = row_hi / S_, s1 = row_hi % S_;
                *(uint2*)(out + ((size_t)((b1i * H_ + h) * S_ + s1)) * HD_ + dd) = thi;
            } else {
                *(float2*)(out + (size_t)row_lo * N + col) = vlo;
                *(float2*)(out + (size_t)(row_lo + 8) * N + col) = vhi;
            }
        }
    }
}

// ---------------------------------------------------------------------------
// Flash attention v5: register S/P/O + cp.async double buffer; Q/K/V arrive
// as ready tf32 bits -> ZERO cvt in inner loops (only P gets one f2tf).
// ---------------------------------------------------------------------------
#define AQ  64
#define AKV 64
#define AST 68
#define ATILE (AKV * AST)

extern __shared__ float attn_sm[];

__global__ void __launch_bounds__(128) attn_kernel(
    const float* __restrict__ Qb, const float* __restrict__ Kb,
    const float* __restrict__ Vb, float* __restrict__ Ob)
{
    float* Ks0 = attn_sm;
    float* Vs0 = attn_sm + ATILE;
    float* Ks1 = attn_sm + 2 * ATILE;
    float* Vs1 = attn_sm + 3 * ATILE;

    const int bh   = blockIdx.y;
    const int qt   = blockIdx.x;
    const int tid  = threadIdx.x;
    const int warp = tid >> 5;
    const int lane = tid & 31;
    const int g    = lane >> 2;
    const int tig  = lane & 3;

    const int lr = tid >> 4;
    const int lc = (tid & 15) * 4;

    const float* Kbase = Kb + (size_t)bh * S_ * HD_;
    const float* Vbase = Vb + (size_t)bh * S_ * HD_;

    // Prologue: tile 0
    {
#pragma unroll
        for (int i = 0; i < 8; i++) {
            int r = i * 8 + lr;
            cp_async16(Ks0 + r * AST + lc, Kbase + (size_t)r * HD_ + lc);
            cp_async16(Vs0 + r * AST + lc, Vbase + (size_t)r * HD_ + lc);
        }
        asm volatile("cp.async.commit_group;");
    }

    // Q fragments: raw tf32 bits (already scaled by 0.125 at producer)
    const int qrow0 = qt * AQ + warp * 16;
    const float* Qp = Qb + ((size_t)bh * S_ + qrow0) * HD_;
    unsigned qa[8][4];
#pragma unroll
    for (int kc = 0; kc < 8; kc++) {
        int c0 = kc * 8 + tig;
        qa[kc][0] = __float_as_uint(Qp[(size_t)g * HD_ + c0]);
        qa[kc][1] = __float_as_uint(Qp[(size_t)(g + 8) * HD_ + c0]);
        qa[kc][2] = __float_as_uint(Qp[(size_t)g * HD_ + c0 + 4]);
        qa[kc][3] = __float_as_uint(Qp[(size_t)(g + 8) * HD_ + c0 + 4]);
    }

    float o[8][4];
#pragma unroll
    for (int j = 0; j < 8; j++)
#pragma unroll
        for (int e = 0; e < 4; e++) o[j][e] = 0.0f;
    float m_lo = -1e30f, m_hi = -1e30f;
    float l_lo = 0.0f,   l_hi = 0.0f;

    const unsigned FULL = 0xffffffffu;
    const int src0 = (lane & ~3) | (tig >> 1);
    const int src1 = src0 + 2;

    const int NT = S_ / AKV;
    for (int kt = 0; kt < NT; kt++) {
        if (kt + 1 < NT) {
            float* Kd = (kt & 1) ? Ks0 : Ks1;
            float* Vd = (kt & 1) ? Vs0 : Vs1;
            const float* Kp = Kbase + (size_t)(kt + 1) * AKV * HD_;
            const float* Vp = Vbase + (size_t)(kt + 1) * AKV * HD_;
#pragma unroll
            for (int i = 0; i < 8; i++) {
                int r = i * 8 + lr;
                cp_async16(Kd + r * AST + lc, Kp + (size_t)r * HD_ + lc);
                cp_async16(Vd + r * AST + lc, Vp + (size_t)r * HD_ + lc);
            }
            asm volatile("cp.async.commit_group;");
            asm volatile("cp.async.wait_group 1;");
        } else {
            asm volatile("cp.async.wait_group 0;");
        }
        __syncthreads();

        const float* Ks = (kt & 1) ? Ks1 : Ks0;
        const float* Vs = (kt & 1) ? Vs1 : Vs0;

        // ---- S = Qs @ K^T (operands are ready tf32 bits) ----
        float s[8][4];
#pragma unroll
        for (int j = 0; j < 8; j++)
#pragma unroll
            for (int e = 0; e < 4; e++) s[j][e] = 0.0f;

#pragma unroll
        for (int kc = 0; kc < 8; kc++) {
            int c0 = kc * 8 + tig;
#pragma unroll
            for (int j = 0; j < 8; j++) {
                unsigned b0 = __float_as_uint(Ks[(j * 8 + g) * AST + c0]);
                unsigned b1 = __float_as_uint(Ks[(j * 8 + g) * AST + c0 + 4]);
                mma_tf32(s[j], qa[kc], b0, b1);
            }
        }

        // ---- Online softmax ----
        float mx_lo = -1e30f, mx_hi = -1e30f;
#pragma unroll
        for (int j = 0; j < 8; j++) {
            mx_lo = fmaxf(mx_lo, fmaxf(s[j][0], s[j][1]));
            mx_hi = fmaxf(mx_hi, fmaxf(s[j][2], s[j][3]));
        }
        mx_lo = fmaxf(mx_lo, __shfl_xor_sync(FULL, mx_lo, 1));
        mx_lo = fmaxf(mx_lo, __shfl_xor_sync(FULL, mx_lo, 2));
        mx_hi = fmaxf(mx_hi, __shfl_xor_sync(FULL, mx_hi, 1));
        mx_hi = fmaxf(mx_hi, __shfl_xor_sync(FULL, mx_hi, 2));

        float mn_lo = fmaxf(m_lo, mx_lo);
        float mn_hi = fmaxf(m_hi, mx_hi);
        float al_lo = __expf(m_lo - mn_lo);
        float al_hi = __expf(m_hi - mn_hi);
        m_lo = mn_lo; m_hi = mn_hi;

        float sum_lo = 0.0f, sum_hi = 0.0f;
#pragma unroll
        for (int j = 0; j < 8; j++) {
            float p0 = __expf(s[j][0] - mn_lo);
            float p1 = __expf(s[j][1] - mn_lo);
            float p2 = __expf(s[j][2] - mn_hi);
            float p3 = __expf(s[j][3] - mn_hi);
            sum_lo += p0 + p1;
            sum_hi += p2 + p3;
            s[j][0] = __uint_as_float(f2tf(p0));
            s[j][1] = __uint_as_float(f2tf(p1));
            s[j][2] = __uint_as_float(f2tf(p2));
            s[j][3] = __uint_as_float(f2tf(p3));
        }
        sum_lo += __shfl_xor_sync(FULL, sum_lo, 1);
        sum_lo += __shfl_xor_sync(FULL, sum_lo, 2);
        sum_hi += __shfl_xor_sync(FULL, sum_hi, 1);
        sum_hi += __shfl_xor_sync(FULL, sum_hi, 2);
        l_lo = l_lo * al_lo + sum_lo;
        l_hi = l_hi * al_hi + sum_hi;

#pragma unroll
        for (int j = 0; j < 8; j++) {
            o[j][0] *= al_lo; o[j][1] *= al_lo;
            o[j][2] *= al_hi; o[j][3] *= al_hi;
        }

        // ---- O += P @ V ----
#pragma unroll
        for (int kc = 0; kc < 8; kc++) {
            float v00 = __shfl_sync(FULL, s[kc][0], src0);
            float v01 = __shfl_sync(FULL, s[kc][1], src0);
            float v20 = __shfl_sync(FULL, s[kc][2], src0);
            float v21 = __shfl_sync(FULL, s[kc][3], src0);
            float w00 = __shfl_sync(FULL, s[kc][0], src1);
            float w01 = __shfl_sync(FULL, s[kc][1], src1);
            float w20 = __shfl_sync(FULL, s[kc][2], src1);
            float w21 = __shfl_sync(FULL, s[kc][3], src1);
            unsigned pa[4];
            pa[0] = __float_as_uint((tig & 1) ? v01 : v00);
            pa[1] = __float_as_uint((tig & 1) ? v21 : v20);
            pa[2] = __float_as_uint((tig & 1) ? w01 : w00);
            pa[3] = __float_as_uint((tig & 1) ? w21 : w20);

            int r0 = (kc * 8 + tig) * AST;
            int r1 = (kc * 8 + tig + 4) * AST;
#pragma unroll
            for (int jn = 0; jn < 8; jn++) {
                unsigned b0 = __float_as_uint(Vs[r0 + jn * 8 + g]);
                unsigned b1 = __float_as_uint(Vs[r1 + jn * 8 + g]);
                mma_tf32(o[jn], pa, b0, b1);
            }
        }
        __syncthreads();
    }

    float inv_lo = 1.0f / l_lo;
    float inv_hi = 1.0f / l_hi;
    int b = bh / H_, h = bh % H_;
    float* orow_lo = Ob + ((size_t)(b * S_ + qrow0 + g)) * D_ + h * HD_;
    float* orow_hi = Ob + ((size_t)(b * S_ + qrow0 + g + 8)) * D_ + h * HD_;
#pragma unroll
    for (int jn = 0; jn < 8; jn++) {
        float2 wlo = { o[jn][0] * inv_lo, o[jn][1] * inv_lo };
        float2 whi = { o[jn][2] * inv_hi, o[jn][3] * inv_hi };
        *(float2*)(orow_lo + jn * 8 + 2 * tig) = wlo;
        *(float2*)(orow_hi + jn * 8 + 2 * tig) = whi;
    }
}

// ---------------------------------------------------------------------------
// Launch
// ---------------------------------------------------------------------------
extern "C" void kernel_launch(void* const* d_in, const int* in_sizes, int n_in,
                              void* d_out, int out_size)
{
    (void)in_sizes; (void)n_in; (void)out_size;
    const float* x  = (const float*)d_in[0];
    const float* Wq = (const float*)d_in[1];
    const float* bq = (const float*)d_in[2];
    const float* Wk = (const float*)d_in[3];
    const float* bk = (const float*)d_in[4];
    const float* Wv = (const float*)d_in[5];
    const float* bv = (const float*)d_in[6];
    const float* Wo = (const float*)d_in[7];
    const float* bo = (const float*)d_in[8];
    float* out = (float*)d_out;

    void *pq, *pk, *pv, *patt;
    cudaGetSymbolAddress(&pq, g_q);
    cudaGetSymbolAddress(&pk, g_k);
    cudaGetSymbolAddress(&pv, g_v);
    cudaGetSymbolAddress(&patt, g_att);
    float* qb = (float*)pq;
    float* kb = (float*)pk;
    float* vb = (float*)pv;
    float* ab = (float*)patt;

    const int ATT_SMEM = 4 * ATILE * (int)sizeof(float);   // 69632 B
    cudaFuncSetAttribute(attn_kernel, cudaFuncAttributeMaxDynamicSharedMemorySize, ATT_SMEM);

    dim3 ggrid(D_ / GBN, M_TOT / GBM);   // (8, 32)
    gemm_tf32_kernel<<<ggrid, 256>>>(x, Wq, bq, qb, M_TOT, D_, D_, 1, 0.125f);
    gemm_tf32_kernel<<<ggrid, 256>>>(x, Wk, bk, kb, M_TOT, D_, D_, 1, 1.0f);
    gemm_tf32_kernel<<<ggrid, 256>>>(x, Wv, bv, vb, M_TOT, D_, D_, 1, 1.0f);

    dim3 agrid(S_ / AQ, B_ * H_);        // (32, 32)
    attn_kernel<<<agrid, 128, ATT_SMEM>>>(qb, kb, vb, ab);

    gemm_tf32_kernel<<<ggrid, 256>>>(ab, Wo, bo, out, M_TOT, D_, D_, 0, 1.0f);
}